// round 1
// baseline (speedup 1.0000x reference)
#include <cuda_runtime.h>
#include <math.h>

// Problem dims
constexpr int kT = 4;
constexpr int kB = 8;
constexpr int kC = 384;
constexpr int kN = 1024;          // H*W
constexpr int kBCN = kB * kC * kN;    // 3,145,728
constexpr int kTBCN = kT * kBCN;      // 12,582,912
constexpr float kEPS = 1e-5f;

// Scratch (device globals; no allocation allowed)
__device__ float g_sx[kTBCN];           // input spikes  [t][b][c][n]
__device__ float g_u[3 * kTBCN];        // q/k/v pre-activations [p][t][b][c][n]
__device__ float g_q[kTBCN];            // q spikes      [t][b][c][n]
__device__ float g_kvsum[kT * kB * kC]; // sum_n k*v     [t][b][c]
__device__ float g_kvs[kT * kB * kC];   // kv spikes     [t][b][c]

// ---------------------------------------------------------------------------
// K1: LIF over the raw input x -> binary spike matrix g_sx. Also zeroes g_kvsum.
// One thread per (b,c,n); sequential over t.
// ---------------------------------------------------------------------------
__global__ void lif_x_kernel(const float* __restrict__ x) {
    int idx = blockIdx.x * blockDim.x + threadIdx.x;
    if (idx < kT * kB * kC) g_kvsum[idx] = 0.0f;
    if (idx >= kBCN) return;
    float v = 0.0f;
#pragma unroll
    for (int t = 0; t < kT; t++) {
        float xv = x[t * kBCN + idx];
        v += (xv - v) * 0.5f;             // v = v + (x - v)/TAU, TAU = 2
        float s;
        if (v >= 0.5f) { s = 1.0f; v = 0.0f; }
        else           { s = 0.0f; }
        g_sx[t * kBCN + idx] = s;
    }
}

// ---------------------------------------------------------------------------
// K2: stacked Q/K/V 1x1-conv GEMM + BatchNorm epilogue.
// Per (t,b) image: Y[m,n] = sum_k W_p[m,k] * S[k,n], m in [0,384) per branch.
// grid = (N/128, 9, T*B); blockIdx.y in [0,9): branch p = y/3, m-tile = y%3.
// Classic 128x128x8 SGEMM, 256 threads, 8x8 microtile.
// ---------------------------------------------------------------------------
__global__ __launch_bounds__(256, 2) void gemm_qkv_kernel(
    const float* __restrict__ qw, const float* __restrict__ kw, const float* __restrict__ vw,
    const float* __restrict__ qg, const float* __restrict__ qbe, const float* __restrict__ qm, const float* __restrict__ qva,
    const float* __restrict__ kg, const float* __restrict__ kbe, const float* __restrict__ km, const float* __restrict__ kva,
    const float* __restrict__ vg, const float* __restrict__ vbe, const float* __restrict__ vm, const float* __restrict__ vva)
{
    const int bz = blockIdx.z;
    const int t = bz >> 3;
    const int b = bz & 7;
    const int mt = blockIdx.y;
    const int p = mt / 3;              // branch: 0=q 1=k 2=v
    const int mtb = mt - p * 3;        // m-tile within branch
    const int m0 = mtb * 128;
    const int n0 = blockIdx.x * 128;

    const float* W = (p == 0) ? qw : ((p == 1) ? kw : vw);
    const float* S = g_sx + (size_t)(t * kB + b) * kC * kN;

    __shared__ float As[8][128];
    __shared__ float Bs[8][128];

    const int tid = threadIdx.x;
    const int ty = tid >> 4;           // 0..15
    const int tx = tid & 15;           // 0..15

    float acc[8][8];
#pragma unroll
    for (int i = 0; i < 8; i++)
#pragma unroll
        for (int j = 0; j < 8; j++) acc[i][j] = 0.0f;

    const int rowA = tid >> 1;           // 0..127
    const int colA = (tid & 1) * 4;      // 0 or 4
    const int rowB = tid >> 5;           // 0..7
    const int colB = (tid & 31) * 4;     // 0..124

    const float* Aptr = W + (m0 + rowA) * kC + colA;
    const float* Bptr = S + rowB * kN + n0 + colB;

    for (int k0 = 0; k0 < kC; k0 += 8) {
        float4 a4 = *(const float4*)(Aptr + k0);
        float4 b4 = *(const float4*)(Bptr + (size_t)k0 * kN);
        As[colA + 0][rowA] = a4.x;
        As[colA + 1][rowA] = a4.y;
        As[colA + 2][rowA] = a4.z;
        As[colA + 3][rowA] = a4.w;
        *(float4*)&Bs[rowB][colB] = b4;
        __syncthreads();
#pragma unroll
        for (int kk = 0; kk < 8; kk++) {
            float4 af0 = *(const float4*)&As[kk][ty * 8];
            float4 af1 = *(const float4*)&As[kk][ty * 8 + 4];
            float4 bf0 = *(const float4*)&Bs[kk][tx * 8];
            float4 bf1 = *(const float4*)&Bs[kk][tx * 8 + 4];
            float a[8] = {af0.x, af0.y, af0.z, af0.w, af1.x, af1.y, af1.z, af1.w};
            float bb[8] = {bf0.x, bf0.y, bf0.z, bf0.w, bf1.x, bf1.y, bf1.z, bf1.w};
#pragma unroll
            for (int i = 0; i < 8; i++)
#pragma unroll
                for (int j = 0; j < 8; j++) acc[i][j] += a[i] * bb[j];
        }
        __syncthreads();
    }

    // BN epilogue -> pre-activations
    const float* gam = (p == 0) ? qg : ((p == 1) ? kg : vg);
    const float* bet = (p == 0) ? qbe : ((p == 1) ? kbe : vbe);
    const float* mea = (p == 0) ? qm : ((p == 1) ? km : vm);
    const float* var = (p == 0) ? qva : ((p == 1) ? kva : vva);

#pragma unroll
    for (int i = 0; i < 8; i++) {
        int c = m0 + ty * 8 + i;
        float sc = gam[c] / sqrtf(var[c] + kEPS);
        float mn = mea[c];
        float be = bet[c];
        float* Up = g_u + (size_t)(((p * kT + t) * kB + b) * kC + c) * kN + n0 + tx * 8;
        float4 o0, o1;
        o0.x = (acc[i][0] - mn) * sc + be;
        o0.y = (acc[i][1] - mn) * sc + be;
        o0.z = (acc[i][2] - mn) * sc + be;
        o0.w = (acc[i][3] - mn) * sc + be;
        o1.x = (acc[i][4] - mn) * sc + be;
        o1.y = (acc[i][5] - mn) * sc + be;
        o1.z = (acc[i][6] - mn) * sc + be;
        o1.w = (acc[i][7] - mn) * sc + be;
        *(float4*)(Up) = o0;
        *(float4*)(Up + 4) = o1;
    }
}

// ---------------------------------------------------------------------------
// K3: LIF over t for q/k/v pre-activations. Emits q spikes, and accumulates
// sum_n (k_spike AND v_spike) per (t,b,c) via warp ballot + popcount (exact).
// One thread per (b,c,n).
// ---------------------------------------------------------------------------
__global__ void lif_qkv_kernel() {
    int idx = blockIdx.x * blockDim.x + threadIdx.x;
    if (idx >= kBCN) return;
    int c = (idx >> 10) % kC;       // idx / N % C
    int b = idx / (kC * kN);
    float vq = 0.0f, vk = 0.0f, vv = 0.0f;
#pragma unroll
    for (int t = 0; t < kT; t++) {
        size_t base = (size_t)t * kBCN + idx;
        float uq = g_u[base];
        float uk = g_u[(size_t)kTBCN + base];
        float uv = g_u[2 * (size_t)kTBCN + base];

        vq += (uq - vq) * 0.5f;
        float sq; if (vq >= 0.5f) { sq = 1.0f; vq = 0.0f; } else sq = 0.0f;
        vk += (uk - vk) * 0.5f;
        bool sk; if (vk >= 0.5f) { sk = true; vk = 0.0f; } else sk = false;
        vv += (uv - vv) * 0.5f;
        bool sv; if (vv >= 0.5f) { sv = true; vv = 0.0f; } else sv = false;

        g_q[base] = sq;

        unsigned m = __ballot_sync(0xffffffffu, sk && sv);
        if ((threadIdx.x & 31) == 0)
            atomicAdd(&g_kvsum[(t * kB + b) * kC + c], (float)__popc(m));
    }
}

// ---------------------------------------------------------------------------
// K4: talking heads (8x8 mix over head dim) + LIF over t on kv. Tiny.
// One block, 384 threads: thread = (b, d), d in [0,48), holds 8 LIF states (one per out head).
// ---------------------------------------------------------------------------
__global__ void kv_kernel(const float* __restrict__ th_w) {
    __shared__ float th[64];
    if (threadIdx.x < 64) th[threadIdx.x] = th_w[threadIdx.x];
    __syncthreads();
    int d = threadIdx.x % 48;
    int b = threadIdx.x / 48;
    float v[8];
#pragma unroll
    for (int o = 0; o < 8; o++) v[o] = 0.0f;
#pragma unroll
    for (int t = 0; t < kT; t++) {
        float kvv[8];
#pragma unroll
        for (int h = 0; h < 8; h++)
            kvv[h] = g_kvsum[(t * kB + b) * kC + h * 48 + d];
#pragma unroll
        for (int o = 0; o < 8; o++) {
            float a = 0.0f;
#pragma unroll
            for (int h = 0; h < 8; h++) a += th[o * 8 + h] * kvv[h];
            v[o] += (a - v[o]) * 0.5f;
            float s;
            if (v[o] >= 0.5f) { s = 1.0f; v[o] = 0.0f; } else s = 0.0f;
            g_kvs[(t * kB + b) * kC + o * 48 + d] = s;
        }
    }
}

// ---------------------------------------------------------------------------
// K5: proj GEMM. x_att[k,n] = q[k,n] * kvs[k] computed on B-tile load (exact,
// both binary). Epilogue: +bias, BN, +identity -> final output.
// grid = (N/128, 3, T*B).
// ---------------------------------------------------------------------------
__global__ __launch_bounds__(256, 2) void gemm_proj_kernel(
    const float* __restrict__ x,
    const float* __restrict__ pw, const float* __restrict__ pb,
    const float* __restrict__ pg, const float* __restrict__ pbe,
    const float* __restrict__ pm, const float* __restrict__ pva,
    float* __restrict__ out)
{
    const int bz = blockIdx.z;
    const int t = bz >> 3;
    const int b = bz & 7;
    const int m0 = blockIdx.y * 128;
    const int n0 = blockIdx.x * 128;

    const float* S = g_q + (size_t)(t * kB + b) * kC * kN;
    const float* kvsp = g_kvs + (t * kB + b) * kC;

    __shared__ float As[8][128];
    __shared__ float Bs[8][128];

    const int tid = threadIdx.x;
    const int ty = tid >> 4;
    const int tx = tid & 15;

    float acc[8][8];
#pragma unroll
    for (int i = 0; i < 8; i++)
#pragma unroll
        for (int j = 0; j < 8; j++) acc[i][j] = 0.0f;

    const int rowA = tid >> 1;
    const int colA = (tid & 1) * 4;
    const int rowB = tid >> 5;
    const int colB = (tid & 31) * 4;

    const float* Aptr = pw + (m0 + rowA) * kC + colA;
    const float* Bptr = S + rowB * kN + n0 + colB;

    for (int k0 = 0; k0 < kC; k0 += 8) {
        float4 a4 = *(const float4*)(Aptr + k0);
        float4 b4 = *(const float4*)(Bptr + (size_t)k0 * kN);
        float kvsv = kvsp[k0 + rowB];        // binary -> product exact
        As[colA + 0][rowA] = a4.x;
        As[colA + 1][rowA] = a4.y;
        As[colA + 2][rowA] = a4.z;
        As[colA + 3][rowA] = a4.w;
        b4.x *= kvsv; b4.y *= kvsv; b4.z *= kvsv; b4.w *= kvsv;
        *(float4*)&Bs[rowB][colB] = b4;
        __syncthreads();
#pragma unroll
        for (int kk = 0; kk < 8; kk++) {
            float4 af0 = *(const float4*)&As[kk][ty * 8];
            float4 af1 = *(const float4*)&As[kk][ty * 8 + 4];
            float4 bf0 = *(const float4*)&Bs[kk][tx * 8];
            float4 bf1 = *(const float4*)&Bs[kk][tx * 8 + 4];
            float a[8] = {af0.x, af0.y, af0.z, af0.w, af1.x, af1.y, af1.z, af1.w};
            float bb[8] = {bf0.x, bf0.y, bf0.z, bf0.w, bf1.x, bf1.y, bf1.z, bf1.w};
#pragma unroll
            for (int i = 0; i < 8; i++)
#pragma unroll
                for (int j = 0; j < 8; j++) acc[i][j] += a[i] * bb[j];
        }
        __syncthreads();
    }

#pragma unroll
    for (int i = 0; i < 8; i++) {
        int c = m0 + ty * 8 + i;
        float sc = pg[c] / sqrtf(pva[c] + kEPS);
        float mn = pm[c];
        float be = pbe[c];
        float bias = pb[c];
        size_t obase = (size_t)(((t * kB + b) * kC) + c) * kN + n0 + tx * 8;
        const float* xi = x + obase;
        float* op = out + obase;
        float4 o0, o1;
        o0.x = ((acc[i][0] + bias) - mn) * sc + be + xi[0];
        o0.y = ((acc[i][1] + bias) - mn) * sc + be + xi[1];
        o0.z = ((acc[i][2] + bias) - mn) * sc + be + xi[2];
        o0.w = ((acc[i][3] + bias) - mn) * sc + be + xi[3];
        o1.x = ((acc[i][4] + bias) - mn) * sc + be + xi[4];
        o1.y = ((acc[i][5] + bias) - mn) * sc + be + xi[5];
        o1.z = ((acc[i][6] + bias) - mn) * sc + be + xi[6];
        o1.w = ((acc[i][7] + bias) - mn) * sc + be + xi[7];
        *(float4*)(op) = o0;
        *(float4*)(op + 4) = o1;
    }
}

// ---------------------------------------------------------------------------
extern "C" void kernel_launch(void* const* d_in, const int* in_sizes, int n_in,
                              void* d_out, int out_size)
{
    const float* x   = (const float*)d_in[0];
    const float* qw  = (const float*)d_in[1];
    const float* kw  = (const float*)d_in[2];
    const float* vw  = (const float*)d_in[3];
    const float* thw = (const float*)d_in[4];
    const float* pw  = (const float*)d_in[5];
    const float* pb  = (const float*)d_in[6];
    const float* qg  = (const float*)d_in[7];
    const float* qbe = (const float*)d_in[8];
    const float* qm  = (const float*)d_in[9];
    const float* qva = (const float*)d_in[10];
    const float* kg  = (const float*)d_in[11];
    const float* kbe = (const float*)d_in[12];
    const float* km  = (const float*)d_in[13];
    const float* kva = (const float*)d_in[14];
    const float* vg  = (const float*)d_in[15];
    const float* vbe = (const float*)d_in[16];
    const float* vm  = (const float*)d_in[17];
    const float* vva = (const float*)d_in[18];
    const float* pg  = (const float*)d_in[19];
    const float* pbe = (const float*)d_in[20];
    const float* pm  = (const float*)d_in[21];
    const float* pva = (const float*)d_in[22];
    float* out = (float*)d_out;

    lif_x_kernel<<<kBCN / 256, 256>>>(x);

    dim3 g2(kN / 128, 9, kT * kB);
    gemm_qkv_kernel<<<g2, 256>>>(qw, kw, vw,
                                 qg, qbe, qm, qva,
                                 kg, kbe, km, kva,
                                 vg, vbe, vm, vva);

    lif_qkv_kernel<<<kBCN / 256, 256>>>();

    kv_kernel<<<1, 384>>>(thw);

    dim3 g5(kN / 128, kC / 128, kT * kB);
    gemm_proj_kernel<<<g5, 256>>>(x, pw, pb, pg, pbe, pm, pva, out);
}

// round 3
// speedup vs baseline: 2.1208x; 2.1208x over previous
#include <cuda_runtime.h>
#include <cuda_bf16.h>
#include <cstdint>
#include <math.h>

constexpr int kT = 4, kB = 8, kC = 384, kN = 1024;
constexpr int kBCN  = kB * kC * kN;
constexpr int kTBCN = kT * kBCN;            // 12,582,912
constexpr float kEPS = 1e-5f;
constexpr int kWelems = kC * kC;            // 147456

// ---------------- device scratch (no allocation allowed) ----------------
__device__ __nv_bfloat16 g_wqkv[9 * kWelems];   // [branch*3+split][m][k]
__device__ __nv_bfloat16 g_wp[3 * kWelems];     // [split][m][k]
__device__ __nv_bfloat16 g_sx[kTBCN];           // input spikes  [t][b][n][c]
__device__ __nv_bfloat16 g_qb[kTBCN];           // q spikes      [t][b][n][c]
__device__ float g_u[3ull * kTBCN];             // q/k/v pre-activations [p][t][b][c][n]
__device__ float g_kvsum[kT * kB * kC];
__device__ float g_kvs[kT * kB * kC];

// ---------------- helpers ----------------
__device__ __forceinline__ uint32_t smem_u32(const void* p) {
    uint32_t a;
    asm("{ .reg .u64 t; cvta.to.shared.u64 t, %1; cvt.u32.u64 %0, t; }" : "=r"(a) : "l"(p));
    return a;
}
__device__ __forceinline__ void cp16(uint32_t dst, const void* src) {
    asm volatile("cp.async.cg.shared.global [%0], [%1], 16;" :: "r"(dst), "l"(src));
}
__device__ __forceinline__ void ldm_x4(uint32_t* r, uint32_t addr) {
    asm volatile("ldmatrix.sync.aligned.m8n8.x4.shared.b16 {%0,%1,%2,%3}, [%4];"
                 : "=r"(r[0]), "=r"(r[1]), "=r"(r[2]), "=r"(r[3]) : "r"(addr));
}
__device__ __forceinline__ void mma16816(float* c, const uint32_t* a, uint32_t b0, uint32_t b1) {
    asm volatile("mma.sync.aligned.m16n8k16.row.col.f32.bf16.bf16.f32 "
                 "{%0,%1,%2,%3}, {%4,%5,%6,%7}, {%8,%9}, {%0,%1,%2,%3};"
                 : "+f"(c[0]), "+f"(c[1]), "+f"(c[2]), "+f"(c[3])
                 : "r"(a[0]), "r"(a[1]), "r"(a[2]), "r"(a[3]), "r"(b0), "r"(b1));
}

// GEMM tiling
constexpr int BM = 128, BN = 128, BK = 32;
constexpr int PITCH = 40;                       // bf16 elems per smem row (80B, conflict-free)
constexpr int A_ELEMS = 3 * BM * PITCH;         // 15360 elems (3 splits)
constexpr int B_ELEMS = BN * PITCH;             // 5120
constexpr int STAGE_ELEMS = A_ELEMS + B_ELEMS;  // 20480 elems = 40960 B
constexpr int SMEM_BYTES = 2 * STAGE_ELEMS * 2; // 81920

// ---------------------------------------------------------------------------
// K0: split fp32 weights into 3 exact bf16 terms; also zero kvsum accumulators.
// ---------------------------------------------------------------------------
__global__ void split_w_kernel(const float* __restrict__ qw, const float* __restrict__ kw,
                               const float* __restrict__ vw, const float* __restrict__ pw) {
    int idx = blockIdx.x * 256 + threadIdx.x;
    if (idx < kT * kB * kC) g_kvsum[idx] = 0.0f;
    if (idx >= 4 * kWelems) return;
    int mat = idx / kWelems;
    int e = idx - mat * kWelems;
    const float* src = (mat == 0) ? qw : (mat == 1) ? kw : (mat == 2) ? vw : pw;
    float w = src[e];
    __nv_bfloat16 h = __float2bfloat16(w);
    float r1 = w - __bfloat162float(h);
    __nv_bfloat16 m = __float2bfloat16(r1);
    float r2 = r1 - __bfloat162float(m);
    __nv_bfloat16 l = __float2bfloat16(r2);
    if (mat < 3) {
        g_wqkv[(mat * 3 + 0) * kWelems + e] = h;
        g_wqkv[(mat * 3 + 1) * kWelems + e] = m;
        g_wqkv[(mat * 3 + 2) * kWelems + e] = l;
    } else {
        g_wp[0 * kWelems + e] = h;
        g_wp[1 * kWelems + e] = m;
        g_wp[2 * kWelems + e] = l;
    }
}

// ---------------------------------------------------------------------------
// K1: LIF on x [t][b][c][n] -> bf16 spikes transposed to [t][b][n][c].
// ---------------------------------------------------------------------------
__global__ void lif_x_kernel(const float* __restrict__ x) {
    __shared__ __nv_bfloat16 sm[32][36];
    const int lane = threadIdx.x & 31, wid = threadIdx.x >> 5;
    const int n0 = blockIdx.x * 32, c0 = blockIdx.y * 32, b = blockIdx.z;
    float v[4] = {0.f, 0.f, 0.f, 0.f};
    for (int t = 0; t < kT; t++) {
#pragma unroll
        for (int j = 0; j < 4; j++) {
            int c = c0 + wid * 4 + j;
            float xv = x[((size_t)((t * kB + b) * kC + c)) * kN + n0 + lane];
            v[j] += (xv - v[j]) * 0.5f;
            float s = 0.f;
            if (v[j] >= 0.5f) { s = 1.f; v[j] = 0.f; }
            sm[lane][wid * 4 + j] = __float2bfloat16(s);
        }
        __syncthreads();
        int nr = wid * 4 + (lane >> 3);
        int cw = (lane & 7) * 4;
        uint2 val = *(const uint2*)&sm[nr][cw];
        *(uint2*)&g_sx[((size_t)((t * kB + b) * kN + n0 + nr)) * kC + c0 + cw] = val;
        __syncthreads();
    }
}

// ---------------------------------------------------------------------------
// GEMM via mma.sync (HMMA): 128x128 tile, BK=32, 2-stage cp.async pipeline.
// MODE 0: U = BN(W_p @ S^T) -> g_u.   MODE 1: out = BN(PW @ Qs^T + bias) + x.
// A: weights [m][k] (3 bf16 splits, accumulated), B: spikes [n][k].
// ---------------------------------------------------------------------------
template <int MODE>
__global__ __launch_bounds__(256, 2) void gemm_kernel(
    const float* __restrict__ qg, const float* __restrict__ qbe, const float* __restrict__ qm, const float* __restrict__ qva,
    const float* __restrict__ kg, const float* __restrict__ kbe, const float* __restrict__ km, const float* __restrict__ kva,
    const float* __restrict__ vg, const float* __restrict__ vbe, const float* __restrict__ vm, const float* __restrict__ vva,
    const float* __restrict__ bias, const float* __restrict__ xres, float* __restrict__ outp)
{
    extern __shared__ __nv_bfloat16 sh[];
    const uint32_t shb = smem_u32(sh);

    const int tid = threadIdx.x, wid = tid >> 5, lane = tid & 31;
    const int bz = blockIdx.z, t = bz >> 3, b = bz & 7;
    int p, mtile;
    if (MODE == 0) { int yy = blockIdx.y; p = (yy >= 6) ? 2 : ((yy >= 3) ? 1 : 0); mtile = yy - p * 3; }
    else           { p = 0; mtile = blockIdx.y; }
    const int m0 = mtile * BM, n0 = blockIdx.x * BN;

    const __nv_bfloat16* Abase = (MODE == 0) ? (g_wqkv + (size_t)(p * 3) * kWelems) : g_wp;
    const __nv_bfloat16* Bimg  = ((MODE == 0) ? g_sx : g_qb) + (size_t)(t * kB + b) * kN * kC;

    const int mw = wid >> 1, nw = wid & 1;   // 4 x 2 warp grid

    float acc[2][8][4];
#pragma unroll
    for (int i = 0; i < 2; i++)
#pragma unroll
        for (int j = 0; j < 8; j++)
#pragma unroll
            for (int q = 0; q < 4; q++) acc[i][j][q] = 0.f;

    // ---- async tile loader for k-chunk ck into stage st ----
    auto load_chunk = [&](int ck, int st) {
        const uint32_t sb = shb + st * STAGE_ELEMS * 2;
        const int k0 = ck * BK;
        // A: 3 splits x 128 rows x 32 k = 1536 x 16B
#pragma unroll
        for (int it = 0; it < 6; it++) {
            int i = it * 256 + tid;
            int sp = i >> 9, rem = i & 511, r = rem >> 2, kq = rem & 3;
            const void* src = Abase + (size_t)sp * kWelems + (size_t)(m0 + r) * kC + k0 + kq * 8;
            cp16(sb + (sp * BM * PITCH + r * PITCH + kq * 8) * 2, src);
        }
        // B: 128 rows x 32 k = 512 x 16B
#pragma unroll
        for (int it = 0; it < 2; it++) {
            int i = it * 256 + tid;
            int r = i >> 2, kq = i & 3;
            const void* src = Bimg + (size_t)(n0 + r) * kC + k0 + kq * 8;
            cp16(sb + (A_ELEMS + r * PITCH + kq * 8) * 2, src);
        }
        asm volatile("cp.async.commit_group;");
    };

    load_chunk(0, 0);
    const int ldrow = lane & 15, ldhalf = lane >> 4;   // ldmatrix x4 addressing

    for (int c = 0; c < kC / BK; c++) {
        if (c + 1 < kC / BK) {
            load_chunk(c + 1, (c + 1) & 1);
            asm volatile("cp.async.wait_group 1;");
        } else {
            asm volatile("cp.async.wait_group 0;");
        }
        __syncthreads();
        const uint32_t sb = shb + (c & 1) * STAGE_ELEMS * 2;
#pragma unroll
        for (int ks = 0; ks < 2; ks++) {
            const int k0 = ks * 16;
            uint32_t bfr[16];
#pragma unroll
            for (int g = 0; g < 4; g++) {
                uint32_t addr = sb + (A_ELEMS + (nw * 64 + g * 16 + ldrow) * PITCH + k0 + ldhalf * 8) * 2;
                ldm_x4(&bfr[g * 4], addr);
            }
#pragma unroll
            for (int sp = 0; sp < 3; sp++) {
                uint32_t afr[2][4];
#pragma unroll
                for (int mi = 0; mi < 2; mi++) {
                    uint32_t addr = sb + (sp * BM * PITCH + (mw * 32 + mi * 16 + ldrow) * PITCH + k0 + ldhalf * 8) * 2;
                    ldm_x4(afr[mi], addr);
                }
#pragma unroll
                for (int mi = 0; mi < 2; mi++)
#pragma unroll
                    for (int nj = 0; nj < 8; nj++) {
                        int g = nj >> 1, w = nj & 1;
                        mma16816(acc[mi][nj], afr[mi], bfr[g * 4 + w], bfr[g * 4 + w + 2]);
                    }
            }
        }
        __syncthreads();
    }

    // ---- epilogue ----
    const float *G, *Be, *Mn, *Va;
    if (MODE == 0) {
        if (p == 0)      { G = qg; Be = qbe; Mn = qm; Va = qva; }
        else if (p == 1) { G = kg; Be = kbe; Mn = km; Va = kva; }
        else             { G = vg; Be = vbe; Mn = vm; Va = vva; }
    } else             { G = qg; Be = qbe; Mn = qm; Va = qva; }

    const int gr = lane >> 2, gc = (lane & 3) * 2;
    const size_t imgoff = ((size_t)(t * kB + b) * kC) * kN;

#pragma unroll
    for (int mi = 0; mi < 2; mi++) {
#pragma unroll
        for (int half = 0; half < 2; half++) {
            const int c = m0 + mw * 32 + mi * 16 + gr + half * 8;
            const float sc = G[c] / sqrtf(Va[c] + kEPS);
            const float mn = Mn[c], be = Be[c];
            const float bi = (MODE == 1) ? bias[c] : 0.f;
            size_t rowoff;
            if (MODE == 0) rowoff = (size_t)p * kTBCN + imgoff + (size_t)c * kN;
            else           rowoff = imgoff + (size_t)c * kN;
            float* dst = ((MODE == 0) ? g_u : outp) + rowoff;
#pragma unroll
            for (int nj = 0; nj < 8; nj++) {
                const int n = n0 + nw * 64 + nj * 8 + gc;
                float v0 = acc[mi][nj][half * 2 + 0];
                float v1 = acc[mi][nj][half * 2 + 1];
                float2 o;
                if (MODE == 0) {
                    o.x = (v0 - mn) * sc + be;
                    o.y = (v1 - mn) * sc + be;
                } else {
                    float2 xv = *(const float2*)(xres + rowoff + n);
                    o.x = ((v0 + bi) - mn) * sc + be + xv.x;
                    o.y = ((v1 + bi) - mn) * sc + be + xv.y;
                }
                *(float2*)(dst + n) = o;
            }
        }
    }
}

// ---------------------------------------------------------------------------
// K3: LIF on q/k/v pre-activations. q spikes -> g_qb (transposed bf16);
// (k AND v) popcount over n -> g_kvsum.
// ---------------------------------------------------------------------------
__global__ void lif_qkv_kernel() {
    __shared__ __nv_bfloat16 sm[32][36];
    const int lane = threadIdx.x & 31, wid = threadIdx.x >> 5;
    const int n0 = blockIdx.x * 32, c0 = blockIdx.y * 32, b = blockIdx.z;
    float vq[4] = {0,0,0,0}, vk[4] = {0,0,0,0}, vv[4] = {0,0,0,0};
    for (int t = 0; t < kT; t++) {
#pragma unroll
        for (int j = 0; j < 4; j++) {
            int c = c0 + wid * 4 + j;
            size_t off = ((size_t)((t * kB + b) * kC + c)) * kN + n0 + lane;
            float uq = g_u[off];
            float uk = g_u[off + (size_t)kTBCN];
            float uv = g_u[off + 2ull * kTBCN];

            vq[j] += (uq - vq[j]) * 0.5f;
            float sq = 0.f; if (vq[j] >= 0.5f) { sq = 1.f; vq[j] = 0.f; }
            vk[j] += (uk - vk[j]) * 0.5f;
            bool sk = false; if (vk[j] >= 0.5f) { sk = true; vk[j] = 0.f; }
            vv[j] += (uv - vv[j]) * 0.5f;
            bool sv = false; if (vv[j] >= 0.5f) { sv = true; vv[j] = 0.f; }

            sm[lane][wid * 4 + j] = __float2bfloat16(sq);
            unsigned msk = __ballot_sync(0xffffffffu, sk && sv);
            if (lane == 0)
                atomicAdd(&g_kvsum[(t * kB + b) * kC + c], (float)__popc(msk));
        }
        __syncthreads();
        int nr = wid * 4 + (lane >> 3);
        int cw = (lane & 7) * 4;
        uint2 val = *(const uint2*)&sm[nr][cw];
        *(uint2*)&g_qb[((size_t)((t * kB + b) * kN + n0 + nr)) * kC + c0 + cw] = val;
        __syncthreads();
    }
}

// ---------------------------------------------------------------------------
// K4: talking heads (8x8 over heads) + LIF on kv. Tiny.
// ---------------------------------------------------------------------------
__global__ void kv_kernel(const float* __restrict__ th_w) {
    __shared__ float th[64];
    if (threadIdx.x < 64) th[threadIdx.x] = th_w[threadIdx.x];
    __syncthreads();
    int d = threadIdx.x % 48;
    int b = threadIdx.x / 48;
    float v[8];
#pragma unroll
    for (int o = 0; o < 8; o++) v[o] = 0.0f;
#pragma unroll
    for (int t = 0; t < kT; t++) {
        float kvv[8];
#pragma unroll
        for (int h = 0; h < 8; h++)
            kvv[h] = g_kvsum[(t * kB + b) * kC + h * 48 + d];
#pragma unroll
        for (int o = 0; o < 8; o++) {
            float a = 0.0f;
#pragma unroll
            for (int h = 0; h < 8; h++) a += th[o * 8 + h] * kvv[h];
            v[o] += (a - v[o]) * 0.5f;
            float s = 0.f;
            if (v[o] >= 0.5f) { s = 1.f; v[o] = 0.f; }
            g_kvs[(t * kB + b) * kC + o * 48 + d] = s;
        }
    }
}

// ---------------------------------------------------------------------------
// K4b: g_qb *= kvs (both binary -> exact).
// ---------------------------------------------------------------------------
__global__ void scale_q_kernel() {
    int i4 = blockIdx.x * 256 + threadIdx.x;
    size_t base = (size_t)i4 * 4;
    if (base >= (size_t)kTBCN) return;
    int c0 = (int)(base % kC);
    size_t tbn = base / kC;
    const float* kvp = g_kvs + (tbn >> 10) * kC + c0;
    uint2 qv = *(uint2*)&g_qb[base];
    __nv_bfloat16* qp = (__nv_bfloat16*)&qv;
#pragma unroll
    for (int i = 0; i < 4; i++)
        qp[i] = __float2bfloat16(__bfloat162float(qp[i]) * kvp[i]);
    *(uint2*)&g_qb[base] = qv;
}

// ---------------------------------------------------------------------------
extern "C" void kernel_launch(void* const* d_in, const int* in_sizes, int n_in,
                              void* d_out, int out_size)
{
    const float* x   = (const float*)d_in[0];
    const float* qw  = (const float*)d_in[1];
    const float* kw  = (const float*)d_in[2];
    const float* vw  = (const float*)d_in[3];
    const float* thw = (const float*)d_in[4];
    const float* pw  = (const float*)d_in[5];
    const float* pb  = (const float*)d_in[6];
    const float* qg  = (const float*)d_in[7];
    const float* qbe = (const float*)d_in[8];
    const float* qm  = (const float*)d_in[9];
    const float* qva = (const float*)d_in[10];
    const float* kg  = (const float*)d_in[11];
    const float* kbe = (const float*)d_in[12];
    const float* km  = (const float*)d_in[13];
    const float* kva = (const float*)d_in[14];
    const float* vg  = (const float*)d_in[15];
    const float* vbe = (const float*)d_in[16];
    const float* vm  = (const float*)d_in[17];
    const float* vva = (const float*)d_in[18];
    const float* pg  = (const float*)d_in[19];
    const float* pbe = (const float*)d_in[20];
    const float* pm  = (const float*)d_in[21];
    const float* pva = (const float*)d_in[22];
    float* out = (float*)d_out;

    cudaFuncSetAttribute(gemm_kernel<0>, cudaFuncAttributeMaxDynamicSharedMemorySize, SMEM_BYTES);
    cudaFuncSetAttribute(gemm_kernel<1>, cudaFuncAttributeMaxDynamicSharedMemorySize, SMEM_BYTES);

    split_w_kernel<<<(4 * kWelems + 255) / 256, 256>>>(qw, kw, vw, pw);

    lif_x_kernel<<<dim3(kN / 32, kC / 32, kB), 256>>>(x);

    gemm_kernel<0><<<dim3(kN / BN, 9, kT * kB), 256, SMEM_BYTES>>>(
        qg, qbe, qm, qva, kg, kbe, km, kva, vg, vbe, vm, vva,
        nullptr, nullptr, nullptr);

    lif_qkv_kernel<<<dim3(kN / 32, kC / 32, kB), 256>>>();

    kv_kernel<<<1, 384>>>(thw);

    scale_q_kernel<<<kTBCN / 4 / 256, 256>>>();

    gemm_kernel<1><<<dim3(kN / BN, kC / BM, kT * kB), 256, SMEM_BYTES>>>(
        pg, pbe, pm, pva, pg, pbe, pm, pva, pg, pbe, pm, pva,
        pb, x, out);
}